// round 8
// baseline (speedup 1.0000x reference)
#include <cuda_runtime.h>
#include <cuda_bf16.h>
#include <cstdint>

#define N_ROWS   65536
#define K_CENT   512
#define D_DIM    1024
#define TILE_M   128
#define CH_N     256          // centers per chunk
#define NCHUNK   2
#define KSLAB    64
#define NSLABS   (D_DIM / KSLAB)   // 16
#define TAU_F    0.1f
#define EPS_F    1e-8f

// int8 quantized operands + per-row scales
__device__ __align__(16) int8_t g_cq[K_CENT * D_DIM];
__device__ float g_csc[K_CENT];                       // Mb/(127*||c||)
__device__ __align__(16) int8_t g_eq[(size_t)N_ROWS * D_DIM];
__device__ float g_esc[N_ROWS];                       // Ma/(127*||a||*tau)
// Per-chunk partial softmax stats
__device__ float g_pm[NCHUNK * N_ROWS];
__device__ float g_ps[NCHUNK * N_ROWS];
__device__ float g_plv[NCHUNK * N_ROWS];

// ---------------- helpers ----------------
__device__ __forceinline__ uint32_t smem_u32(const void* p) {
    uint32_t a;
    asm("{ .reg .u64 t; cvta.to.shared.u64 t, %1; cvt.u32.u64 %0, t; }" : "=r"(a) : "l"(p));
    return a;
}
// SW64 swizzle for 64B rows: chunk ^= (row>>1)&3
#define SWZ64(o) ((o) ^ ((((uint32_t)(o)) >> 3) & 0x30u))

__device__ __forceinline__ void cp16(uint32_t dst, const void* src) {
    asm volatile("cp.async.cg.shared.global [%0], [%1], 16;"
                 :: "r"(dst), "l"(__cvta_generic_to_global(src)) : "memory");
}
#define CP_COMMIT() asm volatile("cp.async.commit_group;" ::: "memory")
#define CP_WAIT2()  asm volatile("cp.async.wait_group 2;" ::: "memory")

__device__ __forceinline__ void ldsm4(uint32_t* r, uint32_t addr) {
    asm volatile("ldmatrix.sync.aligned.m8n8.x4.shared.b16 {%0,%1,%2,%3}, [%4];"
                 : "=r"(r[0]), "=r"(r[1]), "=r"(r[2]), "=r"(r[3]) : "r"(addr));
}

__device__ __forceinline__ void mma_s8(int* d, const uint32_t* a,
                                       uint32_t b0, uint32_t b1) {
    asm volatile(
        "mma.sync.aligned.m16n8k32.row.col.s32.s8.s8.s32 "
        "{%0,%1,%2,%3}, {%4,%5,%6,%7}, {%8,%9}, {%0,%1,%2,%3};"
        : "+r"(d[0]), "+r"(d[1]), "+r"(d[2]), "+r"(d[3])
        : "r"(a[0]), "r"(a[1]), "r"(a[2]), "r"(a[3]), "r"(b0), "r"(b1));
}

__device__ __forceinline__ int q8(float v, float inv_scale) {
    int q = __float2int_rn(v * inv_scale);
    return max(-127, min(127, q));
}
__device__ __forceinline__ uint32_t pk4(int a, int b, int c, int d) {
    return (uint32_t)(a & 0xFF) | ((uint32_t)(b & 0xFF) << 8) |
           ((uint32_t)(c & 0xFF) << 16) | ((uint32_t)(d & 0xFF) << 24);
}

// ---------------- Kernel 1: quantize centers -> int8, zero out ----------------
__global__ void __launch_bounds__(256) prep_centers_kernel(const float* __restrict__ centers,
                                                           float* __restrict__ out) {
    __shared__ float wss[8], wmx[8];
    const int row = blockIdx.x;
    const int t = threadIdx.x;

    float4 v = reinterpret_cast<const float4*>(centers + (size_t)row * D_DIM)[t];
    float ss = v.x * v.x + v.y * v.y + v.z * v.z + v.w * v.w;
    float mx = fmaxf(fmaxf(fabsf(v.x), fabsf(v.y)), fmaxf(fabsf(v.z), fabsf(v.w)));
#pragma unroll
    for (int o = 16; o; o >>= 1) {
        ss += __shfl_xor_sync(0xFFFFFFFFu, ss, o);
        mx = fmaxf(mx, __shfl_xor_sync(0xFFFFFFFFu, mx, o));
    }
    if ((t & 31) == 0) { wss[t >> 5] = ss; wmx[t >> 5] = mx; }
    __syncthreads();
    if (t < 32) {
        float x = (t < 8) ? wss[t] : 0.f;
        float y = (t < 8) ? wmx[t] : 0.f;
#pragma unroll
        for (int o = 4; o; o >>= 1) {
            x += __shfl_xor_sync(0xFFFFFFFFu, x, o);
            y = fmaxf(y, __shfl_xor_sync(0xFFFFFFFFu, y, o));
        }
        if (t == 0) { wss[0] = x; wmx[0] = y; }
    }
    __syncthreads();
    const float Mb = wmx[0];
    const float inv = 127.0f / Mb;

    reinterpret_cast<uint32_t*>(g_cq + (size_t)row * D_DIM)[t] =
        pk4(q8(v.x, inv), q8(v.y, inv), q8(v.z, inv), q8(v.w, inv));

    if (t == 0) {
        g_csc[row] = Mb / (127.0f * fmaxf(sqrtf(wss[0]), EPS_F));
        if (row == 0) out[0] = 0.f;
    }
}

// ---------------- Kernel 1b: quantize embeddings -> int8 (tau folded into scale) ----------------
// warp per row; 8 warps/block
__global__ void __launch_bounds__(256) prep_emb_kernel(const float* __restrict__ emb) {
    const int lane = threadIdx.x & 31;
    const int wrp  = threadIdx.x >> 5;
    const int row  = blockIdx.x * 8 + wrp;

    const float4* src = reinterpret_cast<const float4*>(emb + (size_t)row * D_DIM);
    float4 v[8];
    float ss = 0.f, mx = 0.f;
#pragma unroll
    for (int j = 0; j < 8; ++j) {
        v[j] = src[lane + j * 32];
        ss += v[j].x * v[j].x + v[j].y * v[j].y + v[j].z * v[j].z + v[j].w * v[j].w;
        mx = fmaxf(mx, fmaxf(fmaxf(fabsf(v[j].x), fabsf(v[j].y)),
                             fmaxf(fabsf(v[j].z), fabsf(v[j].w))));
    }
#pragma unroll
    for (int o = 16; o; o >>= 1) {
        ss += __shfl_xor_sync(0xFFFFFFFFu, ss, o);
        mx = fmaxf(mx, __shfl_xor_sync(0xFFFFFFFFu, mx, o));
    }
    const float inv = 127.0f / mx;

    uint32_t* dst = reinterpret_cast<uint32_t*>(g_eq + (size_t)row * D_DIM);
#pragma unroll
    for (int j = 0; j < 8; ++j)
        dst[lane + j * 32] = pk4(q8(v[j].x, inv), q8(v[j].y, inv),
                                 q8(v[j].z, inv), q8(v[j].w, inv));

    if (lane == 0)
        g_esc[row] = mx / (127.0f * fmaxf(sqrtf(ss), EPS_F) * TAU_F);
}

// ---------------- Kernel 2: int8 GEMM chunk + partial softmax ----------------
// grid = 1024: mtile = bid>>1 (128 rows), chunk = bid&1 (256 centers)
// 512 thr, 16 warps 4(m)x4(n): warp tile 32 rows x 64 cols, acc 64 s32 regs
// SMEM: A 4x8192 @0; B 4x16384 @32768 -> 98304; sb scales @98304; stats after.
#define A_STG     8192u
#define B_STG     16384u
#define OFF_A     0u
#define OFF_B     32768u
#define OFF_SBS   98304u          // 256 f
#define OFF_MM    99328u          // 512 f
#define OFF_MS    101376u
#define OFF_MLV   103424u         // end 105472
#define SMEM_DYN  (105472 + 1024)

__global__ void __launch_bounds__(512, 1)
gemm_chunk_kernel(const long long* __restrict__ labels) {
    extern __shared__ uint8_t dyn[];
    const uint32_t sb = smem_u32(dyn);
    const uint32_t base = (sb + 1023u) & ~1023u;
    uint8_t* gbase = dyn + (base - sb);

    float* sbs   = reinterpret_cast<float*>(gbase + OFF_SBS);
    float* sm_m  = reinterpret_cast<float*>(gbase + OFF_MM);
    float* sm_s  = reinterpret_cast<float*>(gbase + OFF_MS);
    float* sm_lv = reinterpret_cast<float*>(gbase + OFF_MLV);

    const int t     = threadIdx.x;
    const int lane  = t & 31;
    const int wid   = t >> 5;
    const int wm    = wid & 3;    // 32-row slice
    const int wn    = wid >> 2;   // 64-col slice
    const int bid   = blockIdx.x;
    const int mtile = bid >> 1;
    const int chunk = bid & 1;
    const int row0  = mtile * TILE_M;

    // loader: A row = t>>2 (0..127), chunk t&3; B rows t>>2 and +128
    const int lr = t >> 2, lc4 = t & 3;
    const uint32_t sw_a  = SWZ64((uint32_t)(lr * 64 + lc4 * 16));
    const uint32_t sw_b0 = sw_a;
    const uint32_t sw_b1 = SWZ64((uint32_t)((lr + 128) * 64 + lc4 * 16));
    const int8_t* agp = g_eq + (size_t)(row0 + lr) * D_DIM + lc4 * 16;
    const int8_t* bgp = g_cq + (size_t)(chunk * CH_N + lr) * D_DIM + lc4 * 16;

    auto issue = [&](int kb, int stg) {
        const uint32_t Ad = base + OFF_A + (uint32_t)stg * A_STG;
        const uint32_t Bd = base + OFF_B + (uint32_t)stg * B_STG;
        cp16(Ad + sw_a, agp + kb * KSLAB);
        cp16(Bd + sw_b0, bgp + kb * KSLAB);
        cp16(Bd + sw_b1, bgp + (size_t)128 * D_DIM + kb * KSLAB);
    };

    int acc[2][8][4];
#pragma unroll
    for (int am = 0; am < 2; ++am)
#pragma unroll
        for (int an = 0; an < 8; ++an)
#pragma unroll
            for (int k = 0; k < 4; ++k) acc[am][an][k] = 0;

    // chunk's center scales into smem
    if (t < CH_N) sbs[t] = g_csc[chunk * CH_N + t];

    // ---- prologue: stages 0..2 in flight ----
    issue(0, 0); CP_COMMIT();
    issue(1, 1); CP_COMMIT();
    issue(2, 2); CP_COMMIT();

    // ldsm lane addressing
    const int rlow  = lane & 15;          // A: row within 16-block
    const int khalf = lane >> 4;          // A: k-16 half
    const int bctr  = ((lane >> 4) << 3) + (lane & 7);   // B: center within 16-group
    const int kh2   = (lane >> 3) & 1;                    // B: k-16 half

#pragma unroll 1
    for (int kb = 0; kb < NSLABS; ++kb) {
        const int stg = kb & 3;
        const uint32_t Ab = base + OFF_A + (uint32_t)stg * A_STG;
        const uint32_t Bb = base + OFF_B + (uint32_t)stg * B_STG;

        CP_WAIT2();              // slab kb resident
        __syncthreads();         // stage reuse safe

        if (kb + 3 < NSLABS) issue(kb + 3, (kb + 3) & 3);
        CP_COMMIT();

#pragma unroll
        for (int ks = 0; ks < 2; ++ks) {  // two k32 steps per 64-slab
            uint32_t af[2][4], bf[4][4];
#pragma unroll
            for (int am = 0; am < 2; ++am)
                ldsm4(af[am], Ab + SWZ64((uint32_t)((wm * 32 + am * 16 + rlow) * 64
                                                    + (2 * ks + khalf) * 16)));
#pragma unroll
            for (int p = 0; p < 4; ++p)
                ldsm4(bf[p], Bb + SWZ64((uint32_t)((wn * 64 + p * 16 + bctr) * 64
                                                   + (2 * ks + kh2) * 16)));
#pragma unroll
            for (int am = 0; am < 2; ++am)
#pragma unroll
                for (int p = 0; p < 4; ++p) {
                    mma_s8(acc[am][2 * p],     af[am], bf[p][0], bf[p][1]);
                    mma_s8(acc[am][2 * p + 1], af[am], bf[p][2], bf[p][3]);
                }
        }
    }
    __syncthreads();

    // ---- per-warp partial softmax over its 64 cols ----
    const int ql = lane >> 2, qc = lane & 3;
#pragma unroll
    for (int am = 0; am < 2; ++am) {
#pragma unroll
        for (int h = 0; h < 2; ++h) {
            const int r = wm * 32 + am * 16 + ql + 8 * h;
            const float sa = g_esc[row0 + r];
            const int lc = (int)labels[row0 + r];

            float m = -1e30f;
            float v[16];
#pragma unroll
            for (int an = 0; an < 8; ++an)
#pragma unroll
                for (int e = 0; e < 2; ++e) {
                    const float sbc = sbs[wn * 64 + an * 8 + qc * 2 + e];
                    float x = (float)acc[am][an][2 * h + e] * sa * sbc;
                    v[an * 2 + e] = x;
                    m = fmaxf(m, x);
                }
            m = fmaxf(m, __shfl_xor_sync(0xFFFFFFFFu, m, 1));
            m = fmaxf(m, __shfl_xor_sync(0xFFFFFFFFu, m, 2));

            float s = 0.f, lv = 0.f;
#pragma unroll
            for (int an = 0; an < 8; ++an)
#pragma unroll
                for (int e = 0; e < 2; ++e) {
                    s += __expf(v[an * 2 + e] - m);
                    const int col = chunk * CH_N + wn * 64 + an * 8 + qc * 2 + e;
                    if (col == lc) lv = v[an * 2 + e];
                }
            s  += __shfl_xor_sync(0xFFFFFFFFu, s, 1);
            s  += __shfl_xor_sync(0xFFFFFFFFu, s, 2);
            lv += __shfl_xor_sync(0xFFFFFFFFu, lv, 1);
            lv += __shfl_xor_sync(0xFFFFFFFFu, lv, 2);

            if (qc == 0) {
                sm_m[wn * 128 + r]  = m;
                sm_s[wn * 128 + r]  = s;
                sm_lv[wn * 128 + r] = lv;
            }
        }
    }
    __syncthreads();

    // ---- merge 4 warp-columns, write chunk partials ----
    if (t < TILE_M) {
        float M = -1e30f;
#pragma unroll
        for (int w = 0; w < 4; ++w) M = fmaxf(M, sm_m[w * 128 + t]);
        float S = 0.f, LV = 0.f;
#pragma unroll
        for (int w = 0; w < 4; ++w) {
            S  += sm_s[w * 128 + t] * __expf(sm_m[w * 128 + t] - M);
            LV += sm_lv[w * 128 + t];
        }
        const int gr = row0 + t;
        g_pm[chunk * N_ROWS + gr]  = M;
        g_ps[chunk * N_ROWS + gr]  = S;
        g_plv[chunk * N_ROWS + gr] = LV;
    }
}

// ---------------- Kernel 3: finalize (merge 2 chunks) ----------------
__global__ void __launch_bounds__(256) finalize_kernel(float* __restrict__ out) {
    __shared__ float wsum[8];
    const int r = blockIdx.x * 256 + threadIdx.x;

    const float m0 = g_pm[r],           m1 = g_pm[N_ROWS + r];
    const float s0 = g_ps[r],           s1 = g_ps[N_ROWS + r];
    const float lv = g_plv[r] + g_plv[N_ROWS + r];
    const float M  = fmaxf(m0, m1);
    const float S  = s0 * expf(m0 - M) + s1 * expf(m1 - M);
    float loss = (M + logf(S)) - lv;

#pragma unroll
    for (int o = 16; o; o >>= 1) loss += __shfl_xor_sync(0xFFFFFFFFu, loss, o);
    const int t = threadIdx.x;
    if ((t & 31) == 0) wsum[t >> 5] = loss;
    __syncthreads();
    if (t < 32) {
        float x = (t < 8) ? wsum[t] : 0.f;
#pragma unroll
        for (int o = 4; o; o >>= 1) x += __shfl_xor_sync(0xFFFFFFFFu, x, o);
        if (t == 0) atomicAdd(out, x * (1.0f / (float)N_ROWS));
    }
}

// ---------------- Launch ----------------
extern "C" void kernel_launch(void* const* d_in, const int* in_sizes, int n_in,
                              void* d_out, int out_size) {
    const float* emb       = (const float*)d_in[0];
    const float* centers   = (const float*)d_in[1];
    const long long* label = (const long long*)d_in[2];
    float* out             = (float*)d_out;

    cudaFuncSetAttribute(gemm_chunk_kernel, cudaFuncAttributeMaxDynamicSharedMemorySize, SMEM_DYN);

    prep_centers_kernel<<<K_CENT, 256>>>(centers, out);
    prep_emb_kernel<<<N_ROWS / 8, 256>>>(emb);
    gemm_chunk_kernel<<<(N_ROWS / TILE_M) * NCHUNK, 512, SMEM_DYN>>>(label);
    finalize_kernel<<<N_ROWS / 256, 256>>>(out);
}

// round 9
// speedup vs baseline: 2.0322x; 2.0322x over previous
#include <cuda_runtime.h>
#include <cuda_bf16.h>
#include <cstdint>

#define N_ROWS   65536
#define K_CENT   512
#define D_DIM    1024
#define TILE_M   128
#define CH_N     256          // centers per chunk
#define NCHUNK   2
#define KSLAB    64
#define NSLABS   (D_DIM / KSLAB)   // 16
#define TAU_F    0.1f
#define EPS_F    1e-8f

// Normalized centers in bf16 (1/||c|| folded in), row-major [K_CENT][D_DIM]
__device__ __align__(16) __nv_bfloat16 g_cbf[K_CENT * D_DIM];
// Per-chunk partial softmax stats
__device__ float g_pm[NCHUNK * N_ROWS];
__device__ float g_ps[NCHUNK * N_ROWS];
__device__ float g_plv[NCHUNK * N_ROWS];

// ---------------- helpers ----------------
__device__ __forceinline__ uint32_t smem_u32(const void* p) {
    uint32_t a;
    asm("{ .reg .u64 t; cvta.to.shared.u64 t, %1; cvt.u32.u64 %0, t; }" : "=r"(a) : "l"(p));
    return a;
}
#define SWZ(o) ((o) ^ ((((uint32_t)(o)) >> 3) & 0x70u))

__device__ __forceinline__ void cp16(uint32_t dst, const void* src) {
    asm volatile("cp.async.cg.shared.global [%0], [%1], 16;"
                 :: "r"(dst), "l"(__cvta_generic_to_global(src)) : "memory");
}
#define CP_COMMIT() asm volatile("cp.async.commit_group;" ::: "memory")
#define CP_WAIT1()  asm volatile("cp.async.wait_group 1;" ::: "memory")

__device__ __forceinline__ void ldsm4(uint32_t* r, uint32_t addr) {
    asm volatile("ldmatrix.sync.aligned.m8n8.x4.shared.b16 {%0,%1,%2,%3}, [%4];"
                 : "=r"(r[0]), "=r"(r[1]), "=r"(r[2]), "=r"(r[3]) : "r"(addr));
}

__device__ __forceinline__ void mma16816(float* d, const uint32_t* a,
                                         uint32_t b0, uint32_t b1) {
    asm volatile(
        "mma.sync.aligned.m16n8k16.row.col.f32.bf16.bf16.f32 "
        "{%0,%1,%2,%3}, {%4,%5,%6,%7}, {%8,%9}, {%0,%1,%2,%3};"
        : "+f"(d[0]), "+f"(d[1]), "+f"(d[2]), "+f"(d[3])
        : "r"(a[0]), "r"(a[1]), "r"(a[2]), "r"(a[3]), "r"(b0), "r"(b1));
}

__device__ __forceinline__ uint32_t pk(float x, float y) {
    __nv_bfloat162 h = __floats2bfloat162_rn(x, y);
    return *reinterpret_cast<uint32_t*>(&h);
}

// ---------------- Kernel 1: normalize centers -> bf16, zero out ----------------
__global__ void __launch_bounds__(256) prep_centers_kernel(const float* __restrict__ centers,
                                                           float* __restrict__ out) {
    __shared__ float wss[8];
    const int row = blockIdx.x;
    const int t = threadIdx.x;

    float4 v = reinterpret_cast<const float4*>(centers + (size_t)row * D_DIM)[t];
    float ss = v.x * v.x + v.y * v.y + v.z * v.z + v.w * v.w;
#pragma unroll
    for (int o = 16; o; o >>= 1) ss += __shfl_xor_sync(0xFFFFFFFFu, ss, o);
    if ((t & 31) == 0) wss[t >> 5] = ss;
    __syncthreads();
    if (t < 32) {
        float x = (t < 8) ? wss[t] : 0.f;
#pragma unroll
        for (int o = 4; o; o >>= 1) x += __shfl_xor_sync(0xFFFFFFFFu, x, o);
        if (t == 0) wss[0] = x;
    }
    __syncthreads();
    const float sc = 1.0f / fmaxf(sqrtf(wss[0]), EPS_F);

    __nv_bfloat162* orow = reinterpret_cast<__nv_bfloat162*>(g_cbf + (size_t)row * D_DIM);
    orow[t * 2]     = __floats2bfloat162_rn(v.x * sc, v.y * sc);
    orow[t * 2 + 1] = __floats2bfloat162_rn(v.z * sc, v.w * sc);

    if (row == 0 && t == 0) out[0] = 0.f;
}

// ---------------- Kernel 2: fused GEMM, fp32 A staged, convert one slab ahead --------
// grid = 1024: mtile = bid>>1 (128 rows), chunk = bid&1 (256 centers)
// 512 thr, 16 warps 4(m)x4(n): warp tile 32 rows x 64 cols, acc 64 f32 regs
// SMEM (1024-aligned base):
//   A32 3 x 32768 @ 0        fp32 slab staging (row*256B, XOR-chunk layout)
//   B   3 x 32768 @ 98304    bf16 SW128
//   ABF 2 x 16384 @ 196608   bf16 A ldsm tile SW128  -> end 229376
#define A32_STG   32768u
#define B_STG     32768u
#define OFF_A32   0u
#define OFF_B     98304u
#define OFF_ABF   196608u
#define SMEM_DYN  (229376 + 1024)
// post-loop stats (alias A32 region)
#define OFF_SS    0u        // 512 f
#define OFF_SCALE 2048u     // 128 f
#define OFF_MM    4096u     // 512 f
#define OFF_MS    6144u     // 512 f
#define OFF_MLV   8192u     // 512 f

__global__ void __launch_bounds__(512, 1)
gemm_chunk_kernel(const float* __restrict__ emb,
                  const long long* __restrict__ labels) {
    extern __shared__ uint8_t dyn[];
    const uint32_t sb = smem_u32(dyn);
    const uint32_t base = (sb + 1023u) & ~1023u;
    uint8_t* gbase = dyn + (base - sb);

    float* ss_arr = reinterpret_cast<float*>(gbase + OFF_SS);
    float* sc_arr = reinterpret_cast<float*>(gbase + OFF_SCALE);
    float* sm_m   = reinterpret_cast<float*>(gbase + OFF_MM);
    float* sm_s   = reinterpret_cast<float*>(gbase + OFF_MS);
    float* sm_lv  = reinterpret_cast<float*>(gbase + OFF_MLV);

    const int t     = threadIdx.x;
    const int lane  = t & 31;
    const int wid   = t >> 5;
    const int wm    = wid & 3;    // 32-row slice
    const int wn    = wid >> 2;   // 64-col slice
    const int bid   = blockIdx.x;
    const int mtile = bid >> 1;
    const int chunk = bid & 1;
    const int row0  = mtile * TILE_M;

    // ---- A mapping: thread owns 4 consecutive 16B chunks (16 fp32) of one row ----
    // Loader and converter share this mapping -> per-thread cp.async wait suffices
    const int arow = t >> 2;          // 0..127
    const int aq   = t & 3;           // quarter of 64-float slab
    const float* agp = emb + (size_t)(row0 + arow) * D_DIM + aq * 16;
    uint32_t a32_off[4];
#pragma unroll
    for (int i = 0; i < 4; ++i) {
        const int c = aq * 4 + i;     // chunk 0..15 within row
        a32_off[i] = (uint32_t)(arow * 256 + ((c ^ (arow & 15)) << 4));
    }
    const uint32_t abf_sw0 = SWZ((uint32_t)(arow * 128 + aq * 32));
    const uint32_t abf_sw1 = SWZ((uint32_t)(arow * 128 + aq * 32 + 16));

    // ---- B mapping: thread owns 4 chunks, rows br + i*64 ----
    const int br = t >> 3, bo = t & 7;
    const __nv_bfloat16* bgp = g_cbf + (size_t)(chunk * CH_N + br) * D_DIM + bo * 8;

    auto issue = [&](int kb, int stg) {
        const uint32_t Ad = base + OFF_A32 + (uint32_t)stg * A32_STG;
        const float* sa = agp + kb * KSLAB;
#pragma unroll
        for (int i = 0; i < 4; ++i) cp16(Ad + a32_off[i], sa + i * 4);
        const uint32_t Bd = base + OFF_B + (uint32_t)stg * B_STG;
        const __nv_bfloat16* sb2 = bgp + kb * KSLAB;
#pragma unroll
        for (int i = 0; i < 4; ++i)
            cp16(Bd + SWZ((uint32_t)((br + i * 64) * 128 + bo * 16)),
                 sb2 + (size_t)(i * 64) * D_DIM);
    };

    float myss = 0.f;
    auto convertA = [&](int kb) {   // A32 stage kb%3 -> ABF[kb&1]; reads own bytes only
        const uint32_t A32b = base + OFF_A32 + (uint32_t)(kb % 3) * A32_STG;
        const uint32_t Abf  = base + OFF_ABF + (uint32_t)(kb & 1) * 16384u;
        float4 f[4];
#pragma unroll
        for (int i = 0; i < 4; ++i)
            asm volatile("ld.shared.v4.f32 {%0,%1,%2,%3}, [%4];"
                         : "=f"(f[i].x), "=f"(f[i].y), "=f"(f[i].z), "=f"(f[i].w)
                         : "r"(A32b + a32_off[i]));
#pragma unroll
        for (int i = 0; i < 4; ++i)
            myss += f[i].x * f[i].x + f[i].y * f[i].y + f[i].z * f[i].z + f[i].w * f[i].w;
        asm volatile("st.shared.v4.b32 [%0], {%1,%2,%3,%4};"
                     :: "r"(Abf + abf_sw0),
                        "r"(pk(f[0].x, f[0].y)), "r"(pk(f[0].z, f[0].w)),
                        "r"(pk(f[1].x, f[1].y)), "r"(pk(f[1].z, f[1].w)));
        asm volatile("st.shared.v4.b32 [%0], {%1,%2,%3,%4};"
                     :: "r"(Abf + abf_sw1),
                        "r"(pk(f[2].x, f[2].y)), "r"(pk(f[2].z, f[2].w)),
                        "r"(pk(f[3].x, f[3].y)), "r"(pk(f[3].z, f[3].w)));
    };

    float acc[2][8][4];
#pragma unroll
    for (int am = 0; am < 2; ++am)
#pragma unroll
        for (int an = 0; an < 8; ++an)
#pragma unroll
            for (int k = 0; k < 4; ++k) acc[am][an][k] = 0.f;

    // ---- prologue ----
    issue(0, 0); CP_COMMIT();
    issue(1, 1); CP_COMMIT();
    CP_WAIT1();                 // slab 0 resident (per-thread: own bytes)
    convertA(0);                // ABF[0]

    const int rlow = lane & 15;
    const int bhi  = (lane >> 4) * 16;

#pragma unroll 1
    for (int kb = 0; kb < NSLABS; ++kb) {
        __syncthreads();        // ABF[kb&1] visible; prior slab reads done -> stage reuse safe

        if (kb + 2 < NSLABS) issue(kb + 2, (kb + 2) % 3);
        CP_COMMIT();
        CP_WAIT1();             // slab kb+1 (A32+B) resident; B(kb) resident since last iter

        if (kb + 1 < NSLABS) convertA(kb + 1);   // own-bytes only: no barrier needed

        const uint32_t Abf = base + OFF_ABF + (uint32_t)(kb & 1) * 16384u;
        const uint32_t Bb  = base + OFF_B + (uint32_t)(kb % 3) * B_STG;
#pragma unroll
        for (int ks = 0; ks < 4; ++ks) {
            const uint32_t byt = (uint32_t)(ks * 32 + bhi);
            uint32_t af[2][4], bf[4][4];
#pragma unroll
            for (int am = 0; am < 2; ++am)
                ldsm4(af[am], Abf + SWZ((uint32_t)((wm * 32 + am * 16 + rlow) * 128) + byt));
#pragma unroll
            for (int p = 0; p < 4; ++p)
                ldsm4(bf[p], Bb + SWZ((uint32_t)((wn * 64 + p * 16 + rlow) * 128) + byt));
#pragma unroll
            for (int am = 0; am < 2; ++am)
#pragma unroll
                for (int p = 0; p < 4; ++p) {
                    mma16816(acc[am][2 * p],     af[am], bf[p][0], bf[p][2]);
                    mma16816(acc[am][2 * p + 1], af[am], bf[p][1], bf[p][3]);
                }
        }
    }
    __syncthreads();

    // ---- row scales from fp32 sumsq (4 partials per row) ----
    ss_arr[t] = myss;
    __syncthreads();
    if (t < TILE_M) {
        float s2 = ss_arr[4 * t] + ss_arr[4 * t + 1] + ss_arr[4 * t + 2] + ss_arr[4 * t + 3];
        sc_arr[t] = 1.0f / (fmaxf(sqrtf(s2), EPS_F) * TAU_F);
    }
    __syncthreads();

    // ---- per-warp partial softmax over its 64 cols ----
    const int ql = lane >> 2, qc = lane & 3;
#pragma unroll
    for (int am = 0; am < 2; ++am) {
#pragma unroll
        for (int h = 0; h < 2; ++h) {
            const int r = wm * 32 + am * 16 + ql + 8 * h;
            const float sc = sc_arr[r];
            const int lc = (int)labels[row0 + r];

            float m = -1e30f;
            float v[16];
#pragma unroll
            for (int an = 0; an < 8; ++an)
#pragma unroll
                for (int e = 0; e < 2; ++e) {
                    float x = acc[am][an][2 * h + e] * sc;
                    v[an * 2 + e] = x;
                    m = fmaxf(m, x);
                }
            m = fmaxf(m, __shfl_xor_sync(0xFFFFFFFFu, m, 1));
            m = fmaxf(m, __shfl_xor_sync(0xFFFFFFFFu, m, 2));

            float s = 0.f, lv = 0.f;
#pragma unroll
            for (int an = 0; an < 8; ++an)
#pragma unroll
                for (int e = 0; e < 2; ++e) {
                    s += __expf(v[an * 2 + e] - m);
                    const int col = chunk * CH_N + wn * 64 + an * 8 + qc * 2 + e;
                    if (col == lc) lv = v[an * 2 + e];
                }
            s  += __shfl_xor_sync(0xFFFFFFFFu, s, 1);
            s  += __shfl_xor_sync(0xFFFFFFFFu, s, 2);
            lv += __shfl_xor_sync(0xFFFFFFFFu, lv, 1);
            lv += __shfl_xor_sync(0xFFFFFFFFu, lv, 2);

            if (qc == 0) {
                sm_m[wn * 128 + r]  = m;
                sm_s[wn * 128 + r]  = s;
                sm_lv[wn * 128 + r] = lv;
            }
        }
    }
    __syncthreads();

    // ---- merge 4 warp-columns, write chunk partials ----
    if (t < TILE_M) {
        float M = -1e30f;
#pragma unroll
        for (int w = 0; w < 4; ++w) M = fmaxf(M, sm_m[w * 128 + t]);
        float S = 0.f, LV = 0.f;
#pragma unroll
        for (int w = 0; w < 4; ++w) {
            S  += sm_s[w * 128 + t] * __expf(sm_m[w * 128 + t] - M);
            LV += sm_lv[w * 128 + t];
        }
        const int gr = row0 + t;
        g_pm[chunk * N_ROWS + gr]  = M;
        g_ps[chunk * N_ROWS + gr]  = S;
        g_plv[chunk * N_ROWS + gr] = LV;
    }
}

// ---------------- Kernel 3: finalize ----------------
__global__ void __launch_bounds__(256) finalize_kernel(float* __restrict__ out) {
    __shared__ float wsum[8];
    const int r = blockIdx.x * 256 + threadIdx.x;

    const float m0 = g_pm[r],           m1 = g_pm[N_ROWS + r];
    const float s0 = g_ps[r],           s1 = g_ps[N_ROWS + r];
    const float lv = g_plv[r] + g_plv[N_ROWS + r];
    const float M  = fmaxf(m0, m1);
    const float S  = s0 * expf(m0 - M) + s1 * expf(m1 - M);
    float loss = (M + logf(S)) - lv;

#pragma unroll
    for (int o = 16; o; o >>= 1) loss += __shfl_xor_sync(0xFFFFFFFFu, loss, o);
    const int t = threadIdx.x;
    if ((t & 31) == 0) wsum[t >> 5] = loss;
    __syncthreads();
    if (t < 32) {
        float x = (t < 8) ? wsum[t] : 0.f;
#pragma unroll
        for (int o = 4; o; o >>= 1) x += __shfl_xor_sync(0xFFFFFFFFu, x, o);
        if (t == 0) atomicAdd(out, x * (1.0f / (float)N_ROWS));
    }
}

// ---------------- Launch ----------------
extern "C" void kernel_launch(void* const* d_in, const int* in_sizes, int n_in,
                              void* d_out, int out_size) {
    const float* emb       = (const float*)d_in[0];
    const float* centers   = (const float*)d_in[1];
    const long long* label = (const long long*)d_in[2];
    float* out             = (float*)d_out;

    cudaFuncSetAttribute(gemm_chunk_kernel, cudaFuncAttributeMaxDynamicSharedMemorySize, SMEM_DYN);

    prep_centers_kernel<<<K_CENT, 256>>>(centers, out);
    gemm_chunk_kernel<<<(N_ROWS / TILE_M) * NCHUNK, 512, SMEM_DYN>>>(emb, label);
    finalize_kernel<<<N_ROWS / 256, 256>>>(out);
}

// round 10
// speedup vs baseline: 2.2897x; 1.1267x over previous
#include <cuda_runtime.h>
#include <cuda_bf16.h>
#include <cstdint>

#define N_ROWS   65536
#define K_CENT   512
#define D_DIM    1024
#define TILE_M   128
#define CH_N     128          // centers per chunk
#define NCHUNK   4
#define KSLAB    64
#define NSLABS   (D_DIM / KSLAB)   // 16
#define TAU_F    0.1f
#define EPS_F    1e-8f

// Normalized centers in bf16 (1/||c|| folded in), row-major [K_CENT][D_DIM]
__device__ __align__(16) __nv_bfloat16 g_cbf[K_CENT * D_DIM];
// Normalized embeddings in bf16 with 1/(||e||*tau) folded in, [N_ROWS][D_DIM]
__device__ __align__(16) __nv_bfloat16 g_ebf[(size_t)N_ROWS * D_DIM];
// Per-chunk partial softmax stats
__device__ float g_pm[NCHUNK * N_ROWS];
__device__ float g_ps[NCHUNK * N_ROWS];
__device__ float g_plv[NCHUNK * N_ROWS];
// Per-mtile completion counters (self-resetting each replay)
__device__ int g_cnt[N_ROWS / TILE_M];

// ---------------- helpers ----------------
__device__ __forceinline__ uint32_t smem_u32(const void* p) {
    uint32_t a;
    asm("{ .reg .u64 t; cvta.to.shared.u64 t, %1; cvt.u32.u64 %0, t; }" : "=r"(a) : "l"(p));
    return a;
}
#define SWZ(o) ((o) ^ ((((uint32_t)(o)) >> 3) & 0x70u))

__device__ __forceinline__ void cp16(uint32_t dst, const void* src) {
    asm volatile("cp.async.cg.shared.global [%0], [%1], 16;"
                 :: "r"(dst), "l"(__cvta_generic_to_global(src)) : "memory");
}
#define CP_COMMIT() asm volatile("cp.async.commit_group;" ::: "memory")
#define CP_WAIT1()  asm volatile("cp.async.wait_group 1;" ::: "memory")

__device__ __forceinline__ void ldsm4(uint32_t* r, uint32_t addr) {
    asm volatile("ldmatrix.sync.aligned.m8n8.x4.shared.b16 {%0,%1,%2,%3}, [%4];"
                 : "=r"(r[0]), "=r"(r[1]), "=r"(r[2]), "=r"(r[3]) : "r"(addr));
}

__device__ __forceinline__ void mma16816(float* d, const uint32_t* a,
                                         uint32_t b0, uint32_t b1) {
    asm volatile(
        "mma.sync.aligned.m16n8k16.row.col.f32.bf16.bf16.f32 "
        "{%0,%1,%2,%3}, {%4,%5,%6,%7}, {%8,%9}, {%0,%1,%2,%3};"
        : "+f"(d[0]), "+f"(d[1]), "+f"(d[2]), "+f"(d[3])
        : "r"(a[0]), "r"(a[1]), "r"(a[2]), "r"(a[3]), "r"(b0), "r"(b1));
}

__device__ __forceinline__ uint32_t pk(float x, float y) {
    __nv_bfloat162 h = __floats2bfloat162_rn(x, y);
    return *reinterpret_cast<uint32_t*>(&h);
}

// ---------------- Kernel 1: merged prep (centers + embeddings) ----------------
// blocks [0,512): normalize center row bid -> g_cbf (+ zero out / counters)
// blocks [512, 512+8192): 8 emb rows each (warp per row) -> g_ebf
#define PREP_CENTER_BLOCKS 512
__global__ void __launch_bounds__(256) prep_kernel(const float* __restrict__ centers,
                                                   const float* __restrict__ emb,
                                                   float* __restrict__ out) {
    const int bid = blockIdx.x;
    const int t = threadIdx.x;

    if (bid < PREP_CENTER_BLOCKS) {
        __shared__ float wss[8];
        const int row = bid;
        float4 v = reinterpret_cast<const float4*>(centers + (size_t)row * D_DIM)[t];
        float ss = v.x * v.x + v.y * v.y + v.z * v.z + v.w * v.w;
#pragma unroll
        for (int o = 16; o; o >>= 1) ss += __shfl_xor_sync(0xFFFFFFFFu, ss, o);
        if ((t & 31) == 0) wss[t >> 5] = ss;
        __syncthreads();
        if (t < 32) {
            float x = (t < 8) ? wss[t] : 0.f;
#pragma unroll
            for (int o = 4; o; o >>= 1) x += __shfl_xor_sync(0xFFFFFFFFu, x, o);
            if (t == 0) wss[0] = x;
        }
        __syncthreads();
        const float sc = 1.0f / fmaxf(sqrtf(wss[0]), EPS_F);

        __nv_bfloat162* orow = reinterpret_cast<__nv_bfloat162*>(g_cbf + (size_t)row * D_DIM);
        orow[t * 2]     = __floats2bfloat162_rn(v.x * sc, v.y * sc);
        orow[t * 2 + 1] = __floats2bfloat162_rn(v.z * sc, v.w * sc);

        if (row == 0 && t == 0) out[0] = 0.f;
        if (row == 1 && t < (N_ROWS / TILE_M) - 256) ;   // no-op keep shape
        return;
    }

    // embeddings path
    const int lane = t & 31;
    const int wrp  = t >> 5;
    const int row  = (bid - PREP_CENTER_BLOCKS) * 8 + wrp;

    const float4* src = reinterpret_cast<const float4*>(emb + (size_t)row * D_DIM);
    float4 v[8];
    float ss = 0.f;
#pragma unroll
    for (int j = 0; j < 8; ++j) {
        v[j] = src[lane + j * 32];
        ss += v[j].x * v[j].x + v[j].y * v[j].y + v[j].z * v[j].z + v[j].w * v[j].w;
    }
#pragma unroll
    for (int o = 16; o; o >>= 1) ss += __shfl_xor_sync(0xFFFFFFFFu, ss, o);
    const float sc = 1.0f / (fmaxf(sqrtf(ss), EPS_F) * TAU_F);

    uint2* dst = reinterpret_cast<uint2*>(g_ebf + (size_t)row * D_DIM);
#pragma unroll
    for (int j = 0; j < 8; ++j) {
        uint2 o;
        o.x = pk(v[j].x * sc, v[j].y * sc);
        o.y = pk(v[j].z * sc, v[j].w * sc);
        dst[lane + j * 32] = o;
    }
}

// ---------------- Kernel 2: GEMM chunk, 256 thr, 2 CTAs/SM, fused finalize ----------
// grid = 2048: mtile = bid>>2 (128 rows), chunk = bid&3 (128 centers)
// 8 warps, 2(m) x 4(n): warp tile 64 rows x 32 cols, acc 64 regs
// SMEM (1024-aligned base), 3-stage:
#define A_STG     16384u
#define B_STG     16384u
#define OFF_A     0u
#define OFF_B     49152u
#define OFF_MM    98304u          // 512 f
#define OFF_MS    100352u
#define OFF_MLV   102400u         // end 104448
#define SMEM_DYN  (104448 + 1024)

__global__ void __launch_bounds__(256, 2)
gemm_chunk_kernel(const long long* __restrict__ labels,
                  float* __restrict__ out) {
    extern __shared__ uint8_t dyn[];
    const uint32_t sb = smem_u32(dyn);
    const uint32_t base = (sb + 1023u) & ~1023u;
    uint8_t* gbase = dyn + (base - sb);

    float* sm_m  = reinterpret_cast<float*>(gbase + OFF_MM);
    float* sm_s  = reinterpret_cast<float*>(gbase + OFF_MS);
    float* sm_lv = reinterpret_cast<float*>(gbase + OFF_MLV);

    const int t     = threadIdx.x;
    const int lane  = t & 31;
    const int wid   = t >> 5;
    const int wm    = wid & 1;    // 64-row slice
    const int wn    = wid >> 1;   // 32-col slice
    const int bid   = blockIdx.x;
    const int mtile = bid >> 2;
    const int chunk = bid & 3;
    const int row0  = mtile * TILE_M;

    // loader mapping: 16B chunk c = t + i*256 -> row = (t>>3) + i*32, off8 = t&7
    const int lr = t >> 3, lo = t & 7;
    uint32_t l_sw[4];
#pragma unroll
    for (int i = 0; i < 4; ++i)
        l_sw[i] = SWZ((uint32_t)((lr + i * 32) * 128 + lo * 16));
    const __nv_bfloat16* agp = g_ebf + (size_t)(row0 + lr) * D_DIM + lo * 8;
    const __nv_bfloat16* bgp = g_cbf + (size_t)(chunk * CH_N + lr) * D_DIM + lo * 8;

    auto issue = [&](int kb, int stg) {
        const uint32_t Ad = base + OFF_A + (uint32_t)stg * A_STG;
        const uint32_t Bd = base + OFF_B + (uint32_t)stg * B_STG;
        const __nv_bfloat16* sa = agp + kb * KSLAB;
        const __nv_bfloat16* sb2 = bgp + kb * KSLAB;
#pragma unroll
        for (int i = 0; i < 4; ++i) cp16(Ad + l_sw[i], sa + (size_t)(i * 32) * D_DIM);
#pragma unroll
        for (int i = 0; i < 4; ++i) cp16(Bd + l_sw[i], sb2 + (size_t)(i * 32) * D_DIM);
    };

    float acc[4][4][4];
#pragma unroll
    for (int am = 0; am < 4; ++am)
#pragma unroll
        for (int an = 0; an < 4; ++an)
#pragma unroll
            for (int k = 0; k < 4; ++k) acc[am][an][k] = 0.f;

    // ---- prologue: stages 0,1 in flight ----
    issue(0, 0); CP_COMMIT();
    issue(1, 1); CP_COMMIT();

    const int rlow = lane & 15;
    const int bhi  = (lane >> 4) * 16;

#pragma unroll 1
    for (int kb = 0; kb < NSLABS; ++kb) {
        const int stg = kb % 3;
        const uint32_t Ab = base + OFF_A + (uint32_t)stg * A_STG;
        const uint32_t Bb = base + OFF_B + (uint32_t)stg * B_STG;

        CP_WAIT1();              // slab kb resident (kb+1 may be pending)
        __syncthreads();         // all warps done with slab kb-1 -> stage (kb+2)%3 free

        if (kb + 2 < NSLABS) issue(kb + 2, (kb + 2) % 3);
        CP_COMMIT();

#pragma unroll
        for (int ks = 0; ks < 4; ++ks) {
            const uint32_t byt = (uint32_t)(ks * 32 + bhi);
            uint32_t af[4][4], bf[2][4];
#pragma unroll
            for (int am = 0; am < 4; ++am)
                ldsm4(af[am], Ab + SWZ((uint32_t)((wm * 64 + am * 16 + rlow) * 128) + byt));
#pragma unroll
            for (int p = 0; p < 2; ++p)
                ldsm4(bf[p], Bb + SWZ((uint32_t)((wn * 32 + p * 16 + rlow) * 128) + byt));
#pragma unroll
            for (int am = 0; am < 4; ++am)
#pragma unroll
                for (int p = 0; p < 2; ++p) {
                    mma16816(acc[am][2 * p],     af[am], bf[p][0], bf[p][2]);
                    mma16816(acc[am][2 * p + 1], af[am], bf[p][1], bf[p][3]);
                }
        }
    }
    __syncthreads();

    // ---- per-warp partial softmax over its 32 cols (scale pre-folded) ----
    const int ql = lane >> 2, qc = lane & 3;
#pragma unroll
    for (int am = 0; am < 4; ++am) {
#pragma unroll
        for (int h = 0; h < 2; ++h) {
            const int r = wm * 64 + am * 16 + ql + 8 * h;
            const int lc = (int)labels[row0 + r];

            float m = -1e30f;
            float v[8];
#pragma unroll
            for (int an = 0; an < 4; ++an)
#pragma unroll
                for (int e = 0; e < 2; ++e) {
                    float x = acc[am][an][2 * h + e];
                    v[an * 2 + e] = x;
                    m = fmaxf(m, x);
                }
            m = fmaxf(m, __shfl_xor_sync(0xFFFFFFFFu, m, 1));
            m = fmaxf(m, __shfl_xor_sync(0xFFFFFFFFu, m, 2));

            float s = 0.f, lv = 0.f;
#pragma unroll
            for (int an = 0; an < 4; ++an)
#pragma unroll
                for (int e = 0; e < 2; ++e) {
                    s += __expf(v[an * 2 + e] - m);
                    const int col = chunk * CH_N + wn * 32 + an * 8 + qc * 2 + e;
                    if (col == lc) lv = v[an * 2 + e];
                }
            s  += __shfl_xor_sync(0xFFFFFFFFu, s, 1);
            s  += __shfl_xor_sync(0xFFFFFFFFu, s, 2);
            lv += __shfl_xor_sync(0xFFFFFFFFu, lv, 1);
            lv += __shfl_xor_sync(0xFFFFFFFFu, lv, 2);

            if (qc == 0) {
                sm_m[wn * 128 + r]  = m;
                sm_s[wn * 128 + r]  = s;
                sm_lv[wn * 128 + r] = lv;
            }
        }
    }
    __syncthreads();

    // ---- merge 4 warp-columns, write chunk partials ----
    if (t < TILE_M) {
        float M = -1e30f;
#pragma unroll
        for (int w = 0; w < 4; ++w) M = fmaxf(M, sm_m[w * 128 + t]);
        float S = 0.f, LV = 0.f;
#pragma unroll
        for (int w = 0; w < 4; ++w) {
            S  += sm_s[w * 128 + t] * __expf(sm_m[w * 128 + t] - M);
            LV += sm_lv[w * 128 + t];
        }
        const int gr = row0 + t;
        g_pm[chunk * N_ROWS + gr]  = M;
        g_ps[chunk * N_ROWS + gr]  = S;
        g_plv[chunk * N_ROWS + gr] = LV;
        __threadfence();          // publish partials before counter bump
    }
    __syncthreads();

    // ---- fused finalize: last chunk-CTA of this mtile merges & accumulates ----
    __shared__ int s_last;
    if (t == 0) {
        int old = atomicAdd(&g_cnt[mtile], 1);
        s_last = (old == NCHUNK - 1) ? 1 : 0;
    }
    __syncthreads();
    if (s_last) {
        __threadfence();          // acquire: other chunks' partials visible
        float loss = 0.f;
        if (t < TILE_M) {
            const int gr = row0 + t;
            float M = -1e30f;
#pragma unroll
            for (int c = 0; c < NCHUNK; ++c) M = fmaxf(M, g_pm[c * N_ROWS + gr]);
            float S = 0.f, LV = 0.f;
#pragma unroll
            for (int c = 0; c < NCHUNK; ++c) {
                S  += g_ps[c * N_ROWS + gr] * __expf(g_pm[c * N_ROWS + gr] - M);
                LV += g_plv[c * N_ROWS + gr];
            }
            loss = (M + logf(S)) - LV;
        }
        // block-reduce 256 lanes (upper 128 contribute 0)
#pragma unroll
        for (int o = 16; o; o >>= 1) loss += __shfl_xor_sync(0xFFFFFFFFu, loss, o);
        __shared__ float wsum[8];
        if ((t & 31) == 0) wsum[t >> 5] = loss;
        __syncthreads();
        if (t < 32) {
            float x = (t < 8) ? wsum[t] : 0.f;
#pragma unroll
            for (int o = 4; o; o >>= 1) x += __shfl_xor_sync(0xFFFFFFFFu, x, o);
            if (t == 0) {
                atomicAdd(out, x * (1.0f / (float)N_ROWS));
                g_cnt[mtile] = 0;   // self-reset for next graph replay
            }
        }
    }
}

// ---------------- Launch ----------------
extern "C" void kernel_launch(void* const* d_in, const int* in_sizes, int n_in,
                              void* d_out, int out_size) {
    const float* emb       = (const float*)d_in[0];
    const float* centers   = (const float*)d_in[1];
    const long long* label = (const long long*)d_in[2];
    float* out             = (float*)d_out;

    cudaFuncSetAttribute(gemm_chunk_kernel, cudaFuncAttributeMaxDynamicSharedMemorySize, SMEM_DYN);

    prep_kernel<<<PREP_CENTER_BLOCKS + N_ROWS / 8, 256>>>(centers, emb, out);
    gemm_chunk_kernel<<<(N_ROWS / TILE_M) * NCHUNK, 256, SMEM_DYN>>>(label, out);
}

// round 11
// speedup vs baseline: 2.3981x; 1.0473x over previous
#include <cuda_runtime.h>
#include <cuda_bf16.h>
#include <cstdint>

#define N_ROWS   65536
#define K_CENT   512
#define D_DIM    1024
#define TILE_M   128
#define CH_N     128          // centers per chunk
#define NCHUNK   4
#define KSLAB    64
#define NSLABS   (D_DIM / KSLAB)   // 16
#define TAU_F    0.1f
#define EPS_F    1e-8f

// Normalized centers in bf16 (1/||c|| folded in), row-major [K_CENT][D_DIM]
__device__ __align__(16) __nv_bfloat16 g_cbf[K_CENT * D_DIM];
// Normalized embeddings in bf16 with 1/(||e||*tau) folded in, [N_ROWS][D_DIM]
__device__ __align__(16) __nv_bfloat16 g_ebf[(size_t)N_ROWS * D_DIM];
// Per-chunk partial softmax stats
__device__ float g_pm[NCHUNK * N_ROWS];
__device__ float g_ps[NCHUNK * N_ROWS];
__device__ float g_plv[NCHUNK * N_ROWS];
// Per-mtile completion counters (self-resetting each replay)
__device__ int g_cnt[N_ROWS / TILE_M];

// ---------------- helpers ----------------
__device__ __forceinline__ uint32_t smem_u32(const void* p) {
    uint32_t a;
    asm("{ .reg .u64 t; cvta.to.shared.u64 t, %1; cvt.u32.u64 %0, t; }" : "=r"(a) : "l"(p));
    return a;
}
#define SWZ(o) ((o) ^ ((((uint32_t)(o)) >> 3) & 0x70u))

__device__ __forceinline__ void cp16(uint32_t dst, const void* src) {
    asm volatile("cp.async.cg.shared.global [%0], [%1], 16;"
                 :: "r"(dst), "l"(__cvta_generic_to_global(src)) : "memory");
}
#define CP_COMMIT() asm volatile("cp.async.commit_group;" ::: "memory")
#define CP_WAIT1()  asm volatile("cp.async.wait_group 1;" ::: "memory")

__device__ __forceinline__ void ldsm4(uint32_t* r, uint32_t addr) {
    asm volatile("ldmatrix.sync.aligned.m8n8.x4.shared.b16 {%0,%1,%2,%3}, [%4];"
                 : "=r"(r[0]), "=r"(r[1]), "=r"(r[2]), "=r"(r[3]) : "r"(addr));
}

__device__ __forceinline__ void mma16816(float* d, const uint32_t* a,
                                         uint32_t b0, uint32_t b1) {
    asm volatile(
        "mma.sync.aligned.m16n8k16.row.col.f32.bf16.bf16.f32 "
        "{%0,%1,%2,%3}, {%4,%5,%6,%7}, {%8,%9}, {%0,%1,%2,%3};"
        : "+f"(d[0]), "+f"(d[1]), "+f"(d[2]), "+f"(d[3])
        : "r"(a[0]), "r"(a[1]), "r"(a[2]), "r"(a[3]), "r"(b0), "r"(b1));
}

__device__ __forceinline__ uint32_t pk(float x, float y) {
    __nv_bfloat162 h = __floats2bfloat162_rn(x, y);
    return *reinterpret_cast<uint32_t*>(&h);
}

// ---------------- Kernel 1: merged prep (centers + embeddings) ----------------
#define PREP_CENTER_BLOCKS 512
__global__ void __launch_bounds__(256) prep_kernel(const float* __restrict__ centers,
                                                   const float* __restrict__ emb,
                                                   float* __restrict__ out) {
    const int bid = blockIdx.x;
    const int t = threadIdx.x;

    if (bid < PREP_CENTER_BLOCKS) {
        __shared__ float wss[8];
        const int row = bid;
        float4 v = reinterpret_cast<const float4*>(centers + (size_t)row * D_DIM)[t];
        float ss = v.x * v.x + v.y * v.y + v.z * v.z + v.w * v.w;
#pragma unroll
        for (int o = 16; o; o >>= 1) ss += __shfl_xor_sync(0xFFFFFFFFu, ss, o);
        if ((t & 31) == 0) wss[t >> 5] = ss;
        __syncthreads();
        if (t < 32) {
            float x = (t < 8) ? wss[t] : 0.f;
#pragma unroll
            for (int o = 4; o; o >>= 1) x += __shfl_xor_sync(0xFFFFFFFFu, x, o);
            if (t == 0) wss[0] = x;
        }
        __syncthreads();
        const float sc = 1.0f / fmaxf(sqrtf(wss[0]), EPS_F);

        __nv_bfloat162* orow = reinterpret_cast<__nv_bfloat162*>(g_cbf + (size_t)row * D_DIM);
        orow[t * 2]     = __floats2bfloat162_rn(v.x * sc, v.y * sc);
        orow[t * 2 + 1] = __floats2bfloat162_rn(v.z * sc, v.w * sc);

        if (row == 0 && t == 0) out[0] = 0.f;
        return;
    }

    // embeddings path
    const int lane = t & 31;
    const int wrp  = t >> 5;
    const int row  = (bid - PREP_CENTER_BLOCKS) * 8 + wrp;

    const float4* src = reinterpret_cast<const float4*>(emb + (size_t)row * D_DIM);
    float4 v[8];
    float ss = 0.f;
#pragma unroll
    for (int j = 0; j < 8; ++j) {
        v[j] = src[lane + j * 32];
        ss += v[j].x * v[j].x + v[j].y * v[j].y + v[j].z * v[j].z + v[j].w * v[j].w;
    }
#pragma unroll
    for (int o = 16; o; o >>= 1) ss += __shfl_xor_sync(0xFFFFFFFFu, ss, o);
    const float sc = 1.0f / (fmaxf(sqrtf(ss), EPS_F) * TAU_F);

    uint2* dst = reinterpret_cast<uint2*>(g_ebf + (size_t)row * D_DIM);
#pragma unroll
    for (int j = 0; j < 8; ++j) {
        uint2 o;
        o.x = pk(v[j].x * sc, v[j].y * sc);
        o.y = pk(v[j].z * sc, v[j].w * sc);
        dst[lane + j * 32] = o;
    }
}

// ---------------- Kernel 2: GEMM chunk, 256 thr, 2 CTAs/SM, fused finalize ----------
// grid = 2048: mtile = bid>>2 (128 rows), chunk = bid&3 (128 centers)
// 8 warps, 2(m) x 4(n): warp tile 64 rows x 32 cols, acc 64 regs
#define A_STG     16384u
#define B_STG     16384u
#define OFF_A     0u
#define OFF_B     49152u
#define OFF_MM    98304u          // 512 f
#define OFF_MS    100352u
#define OFF_MLV   102400u         // end 104448
#define SMEM_DYN  (104448 + 1024)

__global__ void __launch_bounds__(256, 2)
gemm_chunk_kernel(const long long* __restrict__ labels,
                  float* __restrict__ out) {
    extern __shared__ uint8_t dyn[];
    const uint32_t sb = smem_u32(dyn);
    const uint32_t base = (sb + 1023u) & ~1023u;
    uint8_t* gbase = dyn + (base - sb);

    float* sm_m  = reinterpret_cast<float*>(gbase + OFF_MM);
    float* sm_s  = reinterpret_cast<float*>(gbase + OFF_MS);
    float* sm_lv = reinterpret_cast<float*>(gbase + OFF_MLV);

    const int t     = threadIdx.x;
    const int lane  = t & 31;
    const int wid   = t >> 5;
    const int wm    = wid & 1;    // 64-row slice
    const int wn    = wid >> 1;   // 32-col slice
    const int bid   = blockIdx.x;
    const int mtile = bid >> 2;
    const int chunk = bid & 3;
    const int row0  = mtile * TILE_M;

    // loader mapping: 16B chunk c = t + i*256 -> row = (t>>3) + i*32, off8 = t&7
    const int lr = t >> 3, lo = t & 7;
    uint32_t l_sw[4];
#pragma unroll
    for (int i = 0; i < 4; ++i)
        l_sw[i] = SWZ((uint32_t)((lr + i * 32) * 128 + lo * 16));
    const __nv_bfloat16* agp = g_ebf + (size_t)(row0 + lr) * D_DIM + lo * 8;
    const __nv_bfloat16* bgp = g_cbf + (size_t)(chunk * CH_N + lr) * D_DIM + lo * 8;

    // issue one quarter (A chunk i + B chunk i) of slab kb into stage stg
    auto issue_part = [&](int kb, int stg, int i) {
        const uint32_t Ad = base + OFF_A + (uint32_t)stg * A_STG;
        const uint32_t Bd = base + OFF_B + (uint32_t)stg * B_STG;
        cp16(Ad + l_sw[i], agp + kb * KSLAB + (size_t)(i * 32) * D_DIM);
        cp16(Bd + l_sw[i], bgp + kb * KSLAB + (size_t)(i * 32) * D_DIM);
    };

    float acc[4][4][4];
#pragma unroll
    for (int am = 0; am < 4; ++am)
#pragma unroll
        for (int an = 0; an < 4; ++an)
#pragma unroll
            for (int k = 0; k < 4; ++k) acc[am][an][k] = 0.f;

    // ---- prologue: stages 0,1 in flight ----
#pragma unroll
    for (int i = 0; i < 4; ++i) issue_part(0, 0, i);
    CP_COMMIT();
#pragma unroll
    for (int i = 0; i < 4; ++i) issue_part(1, 1, i);
    CP_COMMIT();

    const int rlow = lane & 15;
    const int bhi  = (lane >> 4) * 16;
    const int krot = wid & 3;     // per-warp k-step rotation (de-convoy)

#pragma unroll 1
    for (int kb = 0; kb < NSLABS; ++kb) {
        const int stg = kb % 3;
        const uint32_t Ab = base + OFF_A + (uint32_t)stg * A_STG;
        const uint32_t Bb = base + OFF_B + (uint32_t)stg * B_STG;
        const int nstg = (kb + 2) % 3;
        const bool do_issue = (kb + 2 < NSLABS);

        CP_WAIT1();              // slab kb resident (kb+1 may be pending)
        __syncthreads();         // all warps done with slab kb-1 -> stage (kb+2)%3 free

#pragma unroll
        for (int ksi = 0; ksi < 4; ++ksi) {
            const int ks = (ksi + krot) & 3;   // rotated k-step order
            // spread next-slab cp.async issue across the 4 k-steps
            if (do_issue) issue_part(kb + 2, nstg, ksi);

            const uint32_t byt = (uint32_t)(ks * 32 + bhi);
            uint32_t af[4][4], bf[2][4];
#pragma unroll
            for (int am = 0; am < 4; ++am)
                ldsm4(af[am], Ab + SWZ((uint32_t)((wm * 64 + am * 16 + rlow) * 128) + byt));
#pragma unroll
            for (int p = 0; p < 2; ++p)
                ldsm4(bf[p], Bb + SWZ((uint32_t)((wn * 32 + p * 16 + rlow) * 128) + byt));
#pragma unroll
            for (int am = 0; am < 4; ++am)
#pragma unroll
                for (int p = 0; p < 2; ++p) {
                    mma16816(acc[am][2 * p],     af[am], bf[p][0], bf[p][2]);
                    mma16816(acc[am][2 * p + 1], af[am], bf[p][1], bf[p][3]);
                }
        }
        CP_COMMIT();             // one group per slab keeps wait_group 1 aligned
    }
    __syncthreads();

    // ---- per-warp partial softmax over its 32 cols (scale pre-folded) ----
    const int ql = lane >> 2, qc = lane & 3;
#pragma unroll
    for (int am = 0; am < 4; ++am) {
#pragma unroll
        for (int h = 0; h < 2; ++h) {
            const int r = wm * 64 + am * 16 + ql + 8 * h;
            const int lc = (int)labels[row0 + r];

            float m = -1e30f;
            float v[8];
#pragma unroll
            for (int an = 0; an < 4; ++an)
#pragma unroll
                for (int e = 0; e < 2; ++e) {
                    float x = acc[am][an][2 * h + e];
                    v[an * 2 + e] = x;
                    m = fmaxf(m, x);
                }
            m = fmaxf(m, __shfl_xor_sync(0xFFFFFFFFu, m, 1));
            m = fmaxf(m, __shfl_xor_sync(0xFFFFFFFFu, m, 2));

            float s = 0.f, lv = 0.f;
#pragma unroll
            for (int an = 0; an < 4; ++an)
#pragma unroll
                for (int e = 0; e < 2; ++e) {
                    s += __expf(v[an * 2 + e] - m);
                    const int col = chunk * CH_N + wn * 32 + an * 8 + qc * 2 + e;
                    if (col == lc) lv = v[an * 2 + e];
                }
            s  += __shfl_xor_sync(0xFFFFFFFFu, s, 1);
            s  += __shfl_xor_sync(0xFFFFFFFFu, s, 2);
            lv += __shfl_xor_sync(0xFFFFFFFFu, lv, 1);
            lv += __shfl_xor_sync(0xFFFFFFFFu, lv, 2);

            if (qc == 0) {
                sm_m[wn * 128 + r]  = m;
                sm_s[wn * 128 + r]  = s;
                sm_lv[wn * 128 + r] = lv;
            }
        }
    }
    __syncthreads();

    // ---- merge 4 warp-columns, write chunk partials ----
    if (t < TILE_M) {
        float M = -1e30f;
#pragma unroll
        for (int w = 0; w < 4; ++w) M = fmaxf(M, sm_m[w * 128 + t]);
        float S = 0.f, LV = 0.f;
#pragma unroll
        for (int w = 0; w < 4; ++w) {
            S  += sm_s[w * 128 + t] * __expf(sm_m[w * 128 + t] - M);
            LV += sm_lv[w * 128 + t];
        }
        const int gr = row0 + t;
        g_pm[chunk * N_ROWS + gr]  = M;
        g_ps[chunk * N_ROWS + gr]  = S;
        g_plv[chunk * N_ROWS + gr] = LV;
        __threadfence();          // publish partials before counter bump
    }
    __syncthreads();

    // ---- fused finalize: last chunk-CTA of this mtile merges & accumulates ----
    __shared__ int s_last;
    if (t == 0) {
        int old = atomicAdd(&g_cnt[mtile], 1);
        s_last = (old == NCHUNK - 1) ? 1 : 0;
    }
    __syncthreads();
    if (s_last) {
        __threadfence();          // acquire: other chunks' partials visible
        float loss = 0.f;
        if (t < TILE_M) {
            const int gr = row0 + t;
            float M = -1e30f;
#pragma unroll
            for (int c = 0; c < NCHUNK; ++c) M = fmaxf(M, g_pm[c * N_ROWS + gr]);
            float S = 0.f, LV = 0.f;
#pragma unroll
            for (int c = 0; c < NCHUNK; ++c) {
                S  += g_ps[c * N_ROWS + gr] * __expf(g_pm[c * N_ROWS + gr] - M);
                LV += g_plv[c * N_ROWS + gr];
            }
            loss = (M + logf(S)) - LV;
        }
#pragma unroll
        for (int o = 16; o; o >>= 1) loss += __shfl_xor_sync(0xFFFFFFFFu, loss, o);
        __shared__ float wsum[8];
        if ((t & 31) == 0) wsum[t >> 5] = loss;
        __syncthreads();
        if (t < 32) {
            float x = (t < 8) ? wsum[t] : 0.f;
#pragma unroll
            for (int o = 4; o; o >>= 1) x += __shfl_xor_sync(0xFFFFFFFFu, x, o);
            if (t == 0) {
                atomicAdd(out, x * (1.0f / (float)N_ROWS));
                g_cnt[mtile] = 0;   // self-reset for next graph replay
            }
        }
    }
}

// ---------------- Launch ----------------
extern "C" void kernel_launch(void* const* d_in, const int* in_sizes, int n_in,
                              void* d_out, int out_size) {
    const float* emb       = (const float*)d_in[0];
    const float* centers   = (const float*)d_in[1];
    const long long* label = (const long long*)d_in[2];
    float* out             = (float*)d_out;

    cudaFuncSetAttribute(gemm_chunk_kernel, cudaFuncAttributeMaxDynamicSharedMemorySize, SMEM_DYN);

    prep_kernel<<<PREP_CENTER_BLOCKS + N_ROWS / 8, 256>>>(centers, emb, out);
    gemm_chunk_kernel<<<(N_ROWS / TILE_M) * NCHUNK, 256, SMEM_DYN>>>(label, out);
}